// round 4
// baseline (speedup 1.0000x reference)
#include <cuda_runtime.h>
#include <cstdint>

// Problem constants (fixed by setup_inputs)
#define BB 8192
#define DD 128
#define SCALE (-10.0f)   // -1/TEMPERATURE
#define NEGBIG (-1e30f)

// JAX PRNG layout: 1 = threefry_partitionable (modern JAX default, bits = o0^o1),
// 0 = legacy split-halves layout.
#define JAX_PARTITIONABLE 1

// -------- scratch (no allocations allowed) --------
__device__ float g_sq[BB];
__device__ float g_num[BB];
__device__ int   g_valid[BB];
__device__ int   g_labs[BB];
__device__ float g_part[128];
__device__ int   g_is64;

// ---------------- threefry2x32, key = (0, 42) ----------------
__device__ __forceinline__ unsigned rotl32(unsigned x, int d) {
    return (x << d) | (x >> (32 - d));
}
__device__ __forceinline__ void threefry2x32(unsigned c0, unsigned c1,
                                             unsigned& o0, unsigned& o1) {
    const unsigned k0 = 0u, k1 = 42u;
    const unsigned k2 = 0x1BD11BDAu ^ k0 ^ k1;
    unsigned x0 = c0 + k0, x1 = c1 + k1;
#define TFR(r) { x0 += x1; x1 = rotl32(x1, r); x1 ^= x0; }
    TFR(13) TFR(15) TFR(26) TFR(6)
    x0 += k1; x1 += k2 + 1u;
    TFR(17) TFR(29) TFR(16) TFR(24)
    x0 += k2; x1 += k0 + 2u;
    TFR(13) TFR(15) TFR(26) TFR(6)
    x0 += k0; x1 += k1 + 3u;
    TFR(17) TFR(29) TFR(16) TFR(24)
    x0 += k1; x1 += k2 + 4u;
    TFR(13) TFR(15) TFR(26) TFR(6)
    x0 += k2; x1 += k0 + 5u;
#undef TFR
    o0 = x0; o1 = x1;
}

__device__ __forceinline__ unsigned jax_bits(unsigned long long idx) {
    unsigned o0, o1;
#if JAX_PARTITIONABLE
    // counter-mode: msg = (hi32(idx), lo32(idx)); 32-bit draw = o0 ^ o1
    threefry2x32((unsigned)(idx >> 32), (unsigned)idx, o0, o1);
    return o0 ^ o1;
#else
    // legacy: iota split into halves
    const unsigned long long H = (unsigned long long)BB * BB / 2ull;
    if (idx < H) { threefry2x32((unsigned)idx, (unsigned)(idx + H), o0, o1); return o0; }
    else         { threefry2x32((unsigned)(idx - H), (unsigned)idx, o0, o1); return o1; }
#endif
}

// -------- kernel 0a: detect label dtype (int32 vs int64, little-endian) -----
__global__ void detect_kernel(const unsigned* __restrict__ labels_raw) {
    // Single thread. int64 labels in [0,64) have every odd 32-bit word == 0.
    int is64 = 1;
    for (int i = 0; i < 128; i++)
        if (labels_raw[2 * i + 1] != 0u) { is64 = 0; break; }
    g_is64 = is64;
}

// -------- kernel 0b: convert labels to int --------
__global__ void conv_kernel(const unsigned* __restrict__ labels_raw) {
    int i = blockIdx.x * blockDim.x + threadIdx.x;
    if (i < BB) g_labs[i] = (int)labels_raw[g_is64 ? 2 * i : i];
}

// ---------------- kernel 1: row squared norms ----------------
__global__ void sq_kernel(const float* __restrict__ emb) {
    int wid  = (blockIdx.x * blockDim.x + threadIdx.x) >> 5;
    int lane = threadIdx.x & 31;
    if (wid >= BB) return;
    float4 v = ((const float4*)(emb + (size_t)wid * DD))[lane];
    float d = v.x * v.x + v.y * v.y + v.z * v.z + v.w * v.w;
    #pragma unroll
    for (int off = 16; off; off >>= 1) d += __shfl_xor_sync(0xffffffffu, d, off);
    if (lane == 0) g_sq[wid] = d;
}

// ---- kernel 2: gumbel-argmax positive, numerator, validity ----
__global__ void select_kernel(const float* __restrict__ emb) {
    int wid  = (blockIdx.x * blockDim.x + threadIdx.x) >> 5;
    int lane = threadIdx.x & 31;
    if (wid >= BB) return;
    const int i = wid;
    int labi = g_labs[i];
    unsigned long long best = 0ull;  // ((bits>>9)<<32) | (0xFFFFFFFF - j); 0 == none
    int cnt = 0;
    for (int j = lane; j < BB; j += 32) {
        if (g_labs[j] == labi) {
            cnt++;
            if (j != i) {
                unsigned long long idx = (unsigned long long)i * BB + (unsigned)j;
                unsigned bits = jax_bits(idx);
                unsigned long long key =
                    ((unsigned long long)(bits >> 9) << 32) | (0xFFFFFFFFu - (unsigned)j);
                if (key > best) best = key;
            }
        }
    }
    #pragma unroll
    for (int off = 16; off; off >>= 1) {
        unsigned long long o = __shfl_xor_sync(0xffffffffu, best, off);
        if (o > best) best = o;
        cnt += __shfl_xor_sync(0xffffffffu, cnt, off);
    }
    int jbest = best ? (int)(0xFFFFFFFFu - (unsigned)(best & 0xFFFFFFFFull)) : -1;
    float nm = 0.f;
    if (jbest >= 0) {
        float4 av = ((const float4*)(emb + (size_t)i * DD))[lane];
        float4 bv = ((const float4*)(emb + (size_t)jbest * DD))[lane];
        float d = av.x * bv.x + av.y * bv.y + av.z * bv.z + av.w * bv.w;
        #pragma unroll
        for (int off = 16; off; off >>= 1) d += __shfl_xor_sync(0xffffffffu, d, off);
        float d2 = fmaxf(g_sq[i] + g_sq[jbest] - 2.f * d, 0.f);
        nm = SCALE * d2;
    }
    if (lane == 0) {
        g_num[i]   = nm;
        g_valid[i] = (jbest >= 0 && cnt < BB) ? 1 : 0;
    }
}

// ---- kernel 3: fused distance-GEMM + masked online logsumexp ----
// BM=64 rows/block, BN=128 cols/tile, 256 threads, 4x8 micro-tile.
#define BM 64
#define BN 128
#define LDA 132   // padded row stride (floats), 16B-aligned
#define NT 256

__global__ void __launch_bounds__(NT, 1)
main_kernel(const float* __restrict__ emb) {
    extern __shared__ float smem[];
    float* As = smem;                    // [64][132]
    float* Bs = As + BM * LDA;           // [128][132]
    float* Sq = Bs + BN * LDA;           // [128]
    int*   Ls = (int*)(Sq + BN);         // [128]

    const int tid = threadIdx.x;
    const int ty  = tid >> 4;            // 0..15 -> row group
    const int tx  = tid & 15;            // 0..15 -> col group
    const int i0  = blockIdx.x * BM;
    // half-warp shuffle mask: lanes 0-15 or 16-31 of this thread's warp.
    const unsigned hmask = 0xFFFFu << (threadIdx.x & 16);

    // load A tile (rows i0..i0+63) once
    for (int t = tid; t < BM * 32; t += NT) {
        int r = t >> 5, k4 = t & 31;
        float4 v = ((const float4*)(emb + (size_t)(i0 + r) * DD))[k4];
        *((float4*)(As + r * LDA + k4 * 4)) = v;
    }

    float m[4], s[4], sqR[4];
    int labR[4];
    #pragma unroll
    for (int ri = 0; ri < 4; ri++) {
        m[ri] = NEGBIG; s[ri] = 0.f;
        int row = i0 + 4 * ty + ri;
        sqR[ri]  = g_sq[row];
        labR[ri] = g_labs[row];
    }
    __syncthreads();

    for (int c0 = 0; c0 < BB; c0 += BN) {
        // load B tile
        for (int t = tid; t < BN * 32; t += NT) {
            int r = t >> 5, k4 = t & 31;
            float4 v = ((const float4*)(emb + (size_t)(c0 + r) * DD))[k4];
            *((float4*)(Bs + r * LDA + k4 * 4)) = v;
        }
        if (tid < BN) { Sq[tid] = g_sq[c0 + tid]; Ls[tid] = g_labs[c0 + tid]; }
        __syncthreads();

        float acc[4][8];
        #pragma unroll
        for (int ri = 0; ri < 4; ri++)
            #pragma unroll
            for (int j = 0; j < 8; j++) acc[ri][j] = 0.f;

        #pragma unroll 4
        for (int k4 = 0; k4 < 32; k4++) {
            float4 a[4], b[8];
            #pragma unroll
            for (int ri = 0; ri < 4; ri++)
                a[ri] = *((const float4*)(As + (4 * ty + ri) * LDA + k4 * 4));
            #pragma unroll
            for (int j = 0; j < 8; j++)
                b[j] = *((const float4*)(Bs + (tx + 16 * j) * LDA + k4 * 4));
            #pragma unroll
            for (int ri = 0; ri < 4; ri++)
                #pragma unroll
                for (int j = 0; j < 8; j++) {
                    acc[ri][j] = fmaf(a[ri].x, b[j].x, acc[ri][j]);
                    acc[ri][j] = fmaf(a[ri].y, b[j].y, acc[ri][j]);
                    acc[ri][j] = fmaf(a[ri].z, b[j].z, acc[ri][j]);
                    acc[ri][j] = fmaf(a[ri].w, b[j].w, acc[ri][j]);
                }
        }

        // epilogue: masked sims + online logsumexp across 16 tx lanes.
        // All shuffles use the half-warp mask; every branch containing a
        // shuffle is uniform within that half-warp.
        #pragma unroll
        for (int ri = 0; ri < 4; ri++) {
            float vals[8];
            float tmax = NEGBIG;
            #pragma unroll
            for (int j = 0; j < 8; j++) {
                int cl = tx + 16 * j;
                float d2 = sqR[ri] + Sq[cl] - 2.f * acc[ri][j];
                d2 = fmaxf(d2, 0.f);
                float v = SCALE * d2;
                vals[j] = (labR[ri] != Ls[cl]) ? v : NEGBIG;
                tmax = fmaxf(tmax, vals[j]);
            }
            #pragma unroll
            for (int off = 8; off; off >>= 1)
                tmax = fmaxf(tmax, __shfl_xor_sync(hmask, tmax, off, 16));
            // tmax, m, s are uniform across the 16 lanes of this half-warp.
            if (tmax > m[ri]) { s[ri] *= __expf(m[ri] - tmax); m[ri] = tmax; }
            if (m[ri] > -9e29f && tmax >= m[ri] - 25.f) {  // uniform per half-warp
                float p = 0.f;
                #pragma unroll
                for (int j = 0; j < 8; j++)
                    if (vals[j] >= m[ri] - 25.f) p += __expf(vals[j] - m[ri]);
                #pragma unroll
                for (int off = 8; off; off >>= 1)
                    p += __shfl_xor_sync(hmask, p, off, 16);
                s[ri] += p;
            }
        }
        __syncthreads();
    }

    // per-block deterministic reduction of per_row = denom - num (valid rows)
    __shared__ float red[16];
    if (tx == 0) {
        float local = 0.f;
        #pragma unroll
        for (int ri = 0; ri < 4; ri++) {
            int row = i0 + 4 * ty + ri;
            if (g_valid[row] && s[ri] > 0.f)
                local += m[ri] + logf(s[ri]) - g_num[row];
        }
        red[ty] = local;
    }
    __syncthreads();
    if (tid == 0) {
        float t = 0.f;
        #pragma unroll
        for (int k = 0; k < 16; k++) t += red[k];
        g_part[blockIdx.x] = t;
    }
}

// ---------------- kernel 4: final reduce ----------------
__global__ void finish_kernel(float* __restrict__ out, int nparts) {
    __shared__ float sh[4];
    int tid = threadIdx.x;               // 128 threads
    float v = (tid < nparts) ? g_part[tid] : 0.f;
    #pragma unroll
    for (int off = 16; off; off >>= 1) v += __shfl_xor_sync(0xffffffffu, v, off);
    if ((tid & 31) == 0) sh[tid >> 5] = v;
    __syncthreads();
    if (tid == 0) {
        float t = sh[0] + sh[1] + sh[2] + sh[3];
        out[0] = t / (float)BB;
    }
}

// ---------------- launch ----------------
extern "C" void kernel_launch(void* const* d_in, const int* in_sizes, int n_in,
                              void* d_out, int out_size) {
    const float*    emb        = (const float*)d_in[0];
    const unsigned* labels_raw = (const unsigned*)d_in[1];
    float*          out        = (float*)d_out;

    detect_kernel<<<1, 1>>>(labels_raw);
    conv_kernel<<<(BB + 255) / 256, 256>>>(labels_raw);
    sq_kernel<<<BB * 32 / 256, 256>>>(emb);
    select_kernel<<<BB * 32 / 256, 256>>>(emb);

    const int smem_bytes = (BM * LDA + BN * LDA + BN) * 4 + BN * 4;
    cudaFuncSetAttribute(main_kernel, cudaFuncAttributeMaxDynamicSharedMemorySize,
                         smem_bytes);
    main_kernel<<<BB / BM, NT, smem_bytes>>>(emb);

    finish_kernel<<<1, 128>>>(out, BB / BM);
}

// round 5
// speedup vs baseline: 2.6231x; 2.6231x over previous
#include <cuda_runtime.h>
#include <cstdint>

// Problem constants (fixed by setup_inputs)
#define BB 8192
#define DD 128
#define SCALE (-10.0f)   // -1/TEMPERATURE
#define NEGBIG (-1e30f)

// -------- scratch (no allocations allowed) --------
__device__ float g_sq[BB];
__device__ float g_num[BB];
__device__ int   g_valid[BB];
__device__ int   g_labs[BB];
__device__ float g_part[128];
__device__ int   g_is64;
__device__ int   g_cnt[64];
__device__ int   g_off[64];
__device__ int   g_fill[64];
__device__ int   g_bucket[BB];

// ---------------- threefry2x32, key = (0, 42) ----------------
__device__ __forceinline__ unsigned rotl32(unsigned x, int d) {
    return (x << d) | (x >> (32 - d));
}
__device__ __forceinline__ void threefry2x32(unsigned c0, unsigned c1,
                                             unsigned& o0, unsigned& o1) {
    const unsigned k0 = 0u, k1 = 42u;
    const unsigned k2 = 0x1BD11BDAu ^ k0 ^ k1;
    unsigned x0 = c0 + k0, x1 = c1 + k1;
#define TFR(r) { x0 += x1; x1 = rotl32(x1, r); x1 ^= x0; }
    TFR(13) TFR(15) TFR(26) TFR(6)
    x0 += k1; x1 += k2 + 1u;
    TFR(17) TFR(29) TFR(16) TFR(24)
    x0 += k2; x1 += k0 + 2u;
    TFR(13) TFR(15) TFR(26) TFR(6)
    x0 += k0; x1 += k1 + 3u;
    TFR(17) TFR(29) TFR(16) TFR(24)
    x0 += k1; x1 += k2 + 4u;
    TFR(13) TFR(15) TFR(26) TFR(6)
    x0 += k2; x1 += k0 + 5u;
#undef TFR
    o0 = x0; o1 = x1;
}

__device__ __forceinline__ unsigned jax_bits(unsigned long long idx) {
    // threefry_partitionable: msg = (hi32, lo32), draw = o0 ^ o1
    unsigned o0, o1;
    threefry2x32((unsigned)(idx >> 32), (unsigned)idx, o0, o1);
    return o0 ^ o1;
}

// -------- kernel 0a: detect label dtype (int32 vs int64, little-endian) -----
__global__ void detect_kernel(const unsigned* __restrict__ labels_raw) {
    int is64 = 1;
    for (int i = 0; i < 128; i++)
        if (labels_raw[2 * i + 1] != 0u) { is64 = 0; break; }
    g_is64 = is64;
}

// -------- kernel 0b: convert labels to int --------
__global__ void conv_kernel(const unsigned* __restrict__ labels_raw) {
    int i = blockIdx.x * blockDim.x + threadIdx.x;
    if (i < BB) g_labs[i] = (int)labels_raw[g_is64 ? 2 * i : i] & 63;
}

// -------- bucket construction (labels in [0,64)) --------
__global__ void hist_zero_kernel() {
    if (threadIdx.x < 64) { g_cnt[threadIdx.x] = 0; g_fill[threadIdx.x] = 0; }
}
__global__ void hist_kernel() {
    int i = blockIdx.x * blockDim.x + threadIdx.x;
    if (i < BB) atomicAdd(&g_cnt[g_labs[i]], 1);
}
__global__ void offsets_kernel() {
    int o = 0;
    for (int l = 0; l < 64; l++) { g_off[l] = o; o += g_cnt[l]; }
}
__global__ void scatter_kernel() {
    int i = blockIdx.x * blockDim.x + threadIdx.x;
    if (i < BB) {
        int l = g_labs[i];
        int p = atomicAdd(&g_fill[l], 1);
        g_bucket[g_off[l] + p] = i;
    }
}

// ---------------- kernel 1: row squared norms ----------------
__global__ void sq_kernel(const float* __restrict__ emb) {
    int wid  = (blockIdx.x * blockDim.x + threadIdx.x) >> 5;
    int lane = threadIdx.x & 31;
    if (wid >= BB) return;
    float4 v = ((const float4*)(emb + (size_t)wid * DD))[lane];
    float d = v.x * v.x + v.y * v.y + v.z * v.z + v.w * v.w;
    #pragma unroll
    for (int off = 16; off; off >>= 1) d += __shfl_xor_sync(0xffffffffu, d, off);
    if (lane == 0) g_sq[wid] = d;
}

// ---- kernel 2: gumbel-argmax positive over bucket, numerator, validity ----
__global__ void select_kernel(const float* __restrict__ emb) {
    int wid  = (blockIdx.x * blockDim.x + threadIdx.x) >> 5;
    int lane = threadIdx.x & 31;
    if (wid >= BB) return;
    const int i = wid;
    int labi = g_labs[i];
    int boff = g_off[labi], n = g_cnt[labi];
    unsigned long long best = 0ull;  // ((bits>>9)<<32) | (0xFFFFFFFF - j); 0 == none
    for (int p = lane; p < n; p += 32) {
        int j = g_bucket[boff + p];
        if (j != i) {
            unsigned long long idx = (unsigned long long)i * BB + (unsigned)j;
            unsigned bits = jax_bits(idx);
            unsigned long long key =
                ((unsigned long long)(bits >> 9) << 32) | (0xFFFFFFFFu - (unsigned)j);
            if (key > best) best = key;
        }
    }
    #pragma unroll
    for (int off = 16; off; off >>= 1) {
        unsigned long long o = __shfl_xor_sync(0xffffffffu, best, off);
        if (o > best) best = o;
    }
    int jbest = best ? (int)(0xFFFFFFFFu - (unsigned)(best & 0xFFFFFFFFull)) : -1;
    float nm = 0.f;
    if (jbest >= 0) {
        float4 av = ((const float4*)(emb + (size_t)i * DD))[lane];
        float4 bv = ((const float4*)(emb + (size_t)jbest * DD))[lane];
        float d = av.x * bv.x + av.y * bv.y + av.z * bv.z + av.w * bv.w;
        #pragma unroll
        for (int off = 16; off; off >>= 1) d += __shfl_xor_sync(0xffffffffu, d, off);
        float d2 = fmaxf(g_sq[i] + g_sq[jbest] - 2.f * d, 0.f);
        nm = SCALE * d2;
    }
    if (lane == 0) {
        g_num[i]   = nm;
        g_valid[i] = (jbest >= 0 && n < BB) ? 1 : 0;
    }
}

// ---- kernel 3: tf32 mma.sync distance-GEMM + masked online logsumexp ----
// 128 blocks x BM=64 rows. 8 warps: wm=wid>>1 (4 in M, 16 rows each),
// wn=wid&1 (2 in N, 64 cols each of the BN=128 tile).
// m16n8k8 tf32 fragments; A held in registers for the whole block.
#define BM 64
#define BN 128
#define LDA 132   // padded row stride (floats): bank = (4g+t)&31, conflict-free
#define NT 256

__global__ void __launch_bounds__(NT, 1)
main_kernel(const float* __restrict__ emb) {
    extern __shared__ float smem[];
    float* Bs    = smem;                   // [128][132]; doubles as A staging in prologue
    float* Sq    = Bs + BN * LDA;          // [128]
    int*   Ls    = (int*)(Sq + BN);        // [128]
    float* red_m = (float*)(Ls + BN);      // [64]
    float* red_s = red_m + 64;             // [64]
    float* wsum  = red_s + 64;             // [8]

    const int tid  = threadIdx.x;
    const int wid  = tid >> 5;
    const int lane = tid & 31;
    const int wm   = wid >> 1;             // 0..3
    const int wn   = wid & 1;              // 0..1
    const int g    = lane >> 2;            // groupID 0..7
    const int t    = lane & 3;             // tid-in-group 0..3
    const int i0   = blockIdx.x * BM;
    const unsigned qmask = 0xFu << (lane & 28);

    // ---- prologue: stage A tile in smem, lift to fragment registers ----
    for (int p = tid; p < BM * 32; p += NT) {
        int r = p >> 5, k4 = p & 31;
        ((float4*)(Bs + r * LDA))[k4] =
            ((const float4*)(emb + (size_t)(i0 + r) * DD))[k4];
    }
    __syncthreads();
    unsigned a[16][4];
    {
        const float* pa0 = Bs + (16 * wm + g) * LDA + t;
        const float* pa1 = pa0 + 8 * LDA;
        #pragma unroll
        for (int kk = 0; kk < 16; kk++) {
            a[kk][0] = __float_as_uint(pa0[8 * kk]);
            a[kk][1] = __float_as_uint(pa1[8 * kk]);
            a[kk][2] = __float_as_uint(pa0[8 * kk + 4]);
            a[kk][3] = __float_as_uint(pa1[8 * kk + 4]);
        }
    }
    // per-lane row state: rows r0 = i0+16wm+g, r1 = r0+8 (replicated over quad)
    const int r0 = i0 + 16 * wm + g, r1 = r0 + 8;
    const float sqr[2] = { g_sq[r0], g_sq[r1] };
    const int   lab[2] = { g_labs[r0], g_labs[r1] };
    float m[2] = { NEGBIG, NEGBIG };
    float s[2] = { 0.f, 0.f };
    __syncthreads();

    for (int c0 = 0; c0 < BB; c0 += BN) {
        // load B tile [n][k] (coalesced float4)
        for (int p = tid; p < BN * 32; p += NT) {
            int r = p >> 5, k4 = p & 31;
            ((float4*)(Bs + r * LDA))[k4] =
                ((const float4*)(emb + (size_t)(c0 + r) * DD))[k4];
        }
        if (tid < BN) { Sq[tid] = g_sq[c0 + tid]; Ls[tid] = g_labs[c0 + tid]; }
        __syncthreads();

        float acc[8][4];
        #pragma unroll
        for (int nt = 0; nt < 8; nt++) {
            acc[nt][0] = 0.f; acc[nt][1] = 0.f; acc[nt][2] = 0.f; acc[nt][3] = 0.f;
        }

        const float* pb = Bs + (64 * wn + g) * LDA + t;
        #pragma unroll
        for (int kk = 0; kk < 16; kk++) {
            #pragma unroll
            for (int nt = 0; nt < 8; nt++) {
                unsigned b0 = __float_as_uint(pb[nt * 8 * LDA + 8 * kk]);
                unsigned b1 = __float_as_uint(pb[nt * 8 * LDA + 8 * kk + 4]);
                asm volatile(
                    "mma.sync.aligned.m16n8k8.row.col.f32.tf32.tf32.f32 "
                    "{%0,%1,%2,%3}, {%4,%5,%6,%7}, {%8,%9}, {%0,%1,%2,%3};\n"
                    : "+f"(acc[nt][0]), "+f"(acc[nt][1]),
                      "+f"(acc[nt][2]), "+f"(acc[nt][3])
                    : "r"(a[kk][0]), "r"(a[kk][1]), "r"(a[kk][2]), "r"(a[kk][3]),
                      "r"(b0), "r"(b1));
            }
        }

        // ---- epilogue: masked sims + online logsumexp (quad-scoped) ----
        #pragma unroll
        for (int rs = 0; rs < 2; rs++) {
            float vals[16];
            float tmax = NEGBIG;
            #pragma unroll
            for (int nt = 0; nt < 8; nt++) {
                int cc = 64 * wn + nt * 8 + 2 * t;
                float2 sq2 = *(const float2*)(Sq + cc);
                int2   lb2 = *(const int2*)(Ls + cc);
                float d2a = fmaxf(sqr[rs] + sq2.x - 2.f * acc[nt][2 * rs],     0.f);
                float d2b = fmaxf(sqr[rs] + sq2.y - 2.f * acc[nt][2 * rs + 1], 0.f);
                float va = (lab[rs] != lb2.x) ? SCALE * d2a : NEGBIG;
                float vb = (lab[rs] != lb2.y) ? SCALE * d2b : NEGBIG;
                vals[2 * nt]     = va;
                vals[2 * nt + 1] = vb;
                tmax = fmaxf(tmax, fmaxf(va, vb));
            }
            // quad max (unconditional, all lanes converged)
            tmax = fmaxf(tmax, __shfl_xor_sync(0xffffffffu, tmax, 1, 4));
            tmax = fmaxf(tmax, __shfl_xor_sync(0xffffffffu, tmax, 2, 4));
            if (tmax > m[rs]) { s[rs] *= __expf(m[rs] - tmax); m[rs] = tmax; }
            if (m[rs] > -9e29f && tmax >= m[rs] - 25.f) {  // quad-uniform
                float p = 0.f;
                #pragma unroll
                for (int q = 0; q < 16; q++)
                    if (vals[q] >= m[rs] - 25.f) p += __expf(vals[q] - m[rs]);
                p += __shfl_xor_sync(qmask, p, 1, 4);
                p += __shfl_xor_sync(qmask, p, 2, 4);
                s[rs] += p;
            }
        }
        __syncthreads();
    }

    // ---- merge the two wn halves per row, reduce block sum ----
    const int lr0 = 16 * wm + g, lr1 = lr0 + 8;
    if (wn == 0 && t == 0) {
        red_m[lr0] = m[0]; red_s[lr0] = s[0];
        red_m[lr1] = m[1]; red_s[lr1] = s[1];
    }
    __syncthreads();
    float local = 0.f;
    if (wn == 1 && t == 0) {
        #pragma unroll
        for (int rs = 0; rs < 2; rs++) {
            int lr = (rs == 0) ? lr0 : lr1;
            int rr = (rs == 0) ? r0  : r1;
            float mo = red_m[lr], so = red_s[lr];
            float M = fmaxf(m[rs], mo);
            if (M > -9e29f) {
                float S = 0.f;
                if (m[rs] > -9e29f) S += s[rs] * __expf(m[rs] - M);
                if (mo    > -9e29f) S += so    * __expf(mo    - M);
                if (g_valid[rr] && S > 0.f)
                    local += M + logf(S) - g_num[rr];
            }
        }
    }
    #pragma unroll
    for (int off = 16; off; off >>= 1)
        local += __shfl_xor_sync(0xffffffffu, local, off);
    if (lane == 0) wsum[wid] = local;
    __syncthreads();
    if (tid == 0) {
        float tt = 0.f;
        #pragma unroll
        for (int k = 0; k < 8; k++) tt += wsum[k];
        g_part[blockIdx.x] = tt;
    }
}

// ---------------- kernel 4: final reduce ----------------
__global__ void finish_kernel(float* __restrict__ out, int nparts) {
    __shared__ float sh[4];
    int tid = threadIdx.x;               // 128 threads
    float v = (tid < nparts) ? g_part[tid] : 0.f;
    #pragma unroll
    for (int off = 16; off; off >>= 1) v += __shfl_xor_sync(0xffffffffu, v, off);
    if ((tid & 31) == 0) sh[tid >> 5] = v;
    __syncthreads();
    if (tid == 0) {
        float tt = sh[0] + sh[1] + sh[2] + sh[3];
        out[0] = tt / (float)BB;
    }
}

// ---------------- launch ----------------
extern "C" void kernel_launch(void* const* d_in, const int* in_sizes, int n_in,
                              void* d_out, int out_size) {
    const float*    emb        = (const float*)d_in[0];
    const unsigned* labels_raw = (const unsigned*)d_in[1];
    float*          out        = (float*)d_out;

    detect_kernel<<<1, 1>>>(labels_raw);
    conv_kernel<<<(BB + 255) / 256, 256>>>(labels_raw);
    hist_zero_kernel<<<1, 64>>>();
    hist_kernel<<<(BB + 255) / 256, 256>>>();
    offsets_kernel<<<1, 1>>>();
    scatter_kernel<<<(BB + 255) / 256, 256>>>();
    sq_kernel<<<BB * 32 / 256, 256>>>(emb);
    select_kernel<<<BB * 32 / 256, 256>>>(emb);

    const int smem_bytes = (BN * LDA + BN) * 4 + BN * 4 + (64 + 64 + 8) * 4;
    cudaFuncSetAttribute(main_kernel, cudaFuncAttributeMaxDynamicSharedMemorySize,
                         smem_bytes);
    main_kernel<<<BB / BM, NT, smem_bytes>>>(emb);

    finish_kernel<<<1, 128>>>(out, BB / BM);
}